// round 6
// baseline (speedup 1.0000x reference)
#include <cuda_runtime.h>
#include <cstdint>

// Problem constants (fixed shape (8,2048,2048) fp32, ratio 0.1)
#define N_ELEMS   33554432
#define N_VEC4    (N_ELEMS / 4)
#define K_TOP     3355443           // int(0.1 * N)
#define SBINS     8192              // sample histogram bins (top 13 bits of 31-bit key)
#define SSHIFT    18
#define WIN_BINS  (1 << 20)         // exact window: 4 coarse bins * 2^18 keys
#define WCHUNK    1024
#define NCHUNKS   (WIN_BINS / WCHUNK)
#define EQ_CAP    65536
#define LIST_CAP  (1 << 22)         // 4M i4 entries (expected ~840K)
#define STAGE_CAP 2048              // per-block staging (mean ~800, large margin)
#define SAMPLE_V4 262144            // 1/32 of float4s sampled
#define STARGET   (K_TOP / 32)

#define GRID_MAIN 1024              // 1024*256 = 262144 threads; N_VEC4 divisible
#define BLK_MAIN  256

__device__ unsigned int g_shist[SBINS];
__device__ unsigned int g_winHist[WIN_BINS];
__device__ unsigned int g_chunkSum[NCHUNKS];
__device__ unsigned int g_above;
__device__ unsigned int g_lo;
__device__ unsigned int g_T;
__device__ unsigned int g_need;
__device__ unsigned int g_nList;
__device__ unsigned int g_i4List[LIST_CAP];
__device__ unsigned int g_eqCount;
__device__ unsigned int g_eqIdx[EQ_CAP];
__device__ unsigned int g_eqVal[EQ_CAP];

// ---------------------------------------------------------------------------
__global__ void k_zero() {
    int tid = blockIdx.x * blockDim.x + threadIdx.x;
    int stride = gridDim.x * blockDim.x;
    for (int i = tid; i < WIN_BINS; i += stride) g_winHist[i] = 0;
    for (int i = tid; i < SBINS; i += stride) g_shist[i] = 0;
    if (tid == 0) { g_above = 0; g_eqCount = 0; g_nList = 0; }
}

// ---------------------------------------------------------------------------
// Sample 1/32 of the data into a 13-bit shared histogram, flush to global.
__global__ void k_sample(const float4* __restrict__ x) {
    __shared__ unsigned int sh[SBINS];
    for (int i = threadIdx.x; i < SBINS; i += blockDim.x) sh[i] = 0;
    __syncthreads();

    int tid = blockIdx.x * blockDim.x + threadIdx.x;
    int stride = gridDim.x * blockDim.x;
    for (int i = tid; i < SAMPLE_V4; i += stride) {
        int p = ((i >> 6) << 11) + (i & 63);   // 64 f4 per 2048-f4 group
        float4 v = x[p];
        atomicAdd(&sh[(__float_as_uint(v.x) & 0x7FFFFFFFu) >> SSHIFT], 1u);
        atomicAdd(&sh[(__float_as_uint(v.y) & 0x7FFFFFFFu) >> SSHIFT], 1u);
        atomicAdd(&sh[(__float_as_uint(v.z) & 0x7FFFFFFFu) >> SSHIFT], 1u);
        atomicAdd(&sh[(__float_as_uint(v.w) & 0x7FFFFFFFu) >> SSHIFT], 1u);
    }
    __syncthreads();
    for (int i = threadIdx.x; i < SBINS; i += blockDim.x) {
        unsigned int c = sh[i];
        if (c) atomicAdd(&g_shist[i], c);
    }
}

// ---------------------------------------------------------------------------
// Locate the coarse bin of the estimated k-th value; open a 4-bin window.
__global__ void k_sscan() {
    __shared__ unsigned int suf[1024];
    int t = threadIdx.x;
    unsigned int s = 0;
#pragma unroll
    for (int j = 0; j < 8; j++) s += g_shist[t * 8 + j];
    suf[t] = s;
    __syncthreads();
    for (int d = 1; d < 1024; d <<= 1) {
        unsigned int v = (t + d < 1024) ? suf[t + d] : 0;
        __syncthreads();
        suf[t] += v;
        __syncthreads();
    }
    unsigned int segAbove = (t < 1023) ? suf[t + 1] : 0;
    if (suf[t] >= (unsigned)STARGET && segAbove < (unsigned)STARGET) {
        unsigned int acc = segAbove;
        int bin = t * 8;
        for (int j = 7; j >= 0; j--) {
            acc += g_shist[t * 8 + j];
            if (acc >= (unsigned)STARGET) { bin = t * 8 + j; break; }
        }
        int lo_bin = bin >= 2 ? bin - 2 : 0;
        if (lo_bin > SBINS - 4) lo_bin = SBINS - 4;
        g_lo = (unsigned)lo_bin << SSHIFT;
    }
}

// ---------------------------------------------------------------------------
// FUSED streaming pass: read x, write provisional out (keep iff b>=hi),
// count 'above', and stage vector-indices of float4s touching the window.
// One ballot per float4; shared atomic only when the warp has a hit.
__global__ void __launch_bounds__(BLK_MAIN) k_main(const float4* __restrict__ x,
                                                   float4* __restrict__ out) {
    __shared__ unsigned int s_count;
    __shared__ unsigned int s_above;
    __shared__ unsigned int s_base;
    __shared__ unsigned int s_stage[STAGE_CAP];

    if (threadIdx.x == 0) { s_count = 0; s_above = 0; }
    __syncthreads();

    const unsigned lo = g_lo;
    const unsigned hi = lo + WIN_BINS;
    const unsigned lane = threadIdx.x & 31u;
    unsigned above = 0;

    const unsigned stride = GRID_MAIN * BLK_MAIN;

    // grid is exactly 262144 threads and N_VEC4 % stride == 0, so every
    // warp executes the same number of iterations fully converged.
    for (unsigned i = blockIdx.x * blockDim.x + threadIdx.x; i < (unsigned)N_VEC4;
         i += stride) {
        float4 v = x[i];
        unsigned bx = __float_as_uint(v.x) & 0x7FFFFFFFu;
        unsigned by = __float_as_uint(v.y) & 0x7FFFFFFFu;
        unsigned bz = __float_as_uint(v.z) & 0x7FFFFFFFu;
        unsigned bw = __float_as_uint(v.w) & 0x7FFFFFFFu;
        float4 o;
        o.x = (bx >= hi) ? v.x : 0.0f;
        o.y = (by >= hi) ? v.y : 0.0f;
        o.z = (bz >= hi) ? v.z : 0.0f;
        o.w = (bw >= hi) ? v.w : 0.0f;
        out[i] = o;
        above += (bx >= hi) + (by >= hi) + (bz >= hi) + (bw >= hi);
        // unsigned wrap: b<lo -> huge -> false
        bool win = ((bx - lo) < WIN_BINS) | ((by - lo) < WIN_BINS) |
                   ((bz - lo) < WIN_BINS) | ((bw - lo) < WIN_BINS);
        unsigned m = __ballot_sync(0xFFFFFFFFu, win);
        if (m) {
            int leader = __ffs(m) - 1;
            unsigned base;
            if ((int)lane == leader)
                base = atomicAdd(&s_count, (unsigned)__popc(m));
            base = __shfl_sync(0xFFFFFFFFu, base, leader);
            if (win) {
                unsigned pos = base + __popc(m & ((1u << lane) - 1u));
                if (pos < STAGE_CAP) s_stage[pos] = i;
            }
        }
    }

#pragma unroll
    for (int off = 16; off; off >>= 1) above += __shfl_down_sync(0xFFFFFFFFu, above, off);
    if (lane == 0 && above) atomicAdd(&s_above, above);
    __syncthreads();

    if (threadIdx.x == 0) {
        if (s_above) atomicAdd(&g_above, s_above);
        unsigned n = s_count < STAGE_CAP ? s_count : STAGE_CAP;
        s_base = atomicAdd(&g_nList, n);
        s_count = n;
    }
    __syncthreads();
    unsigned n = s_count, base = s_base;
    for (unsigned j = threadIdx.x; j < n; j += blockDim.x) {
        unsigned pos = base + j;
        if (pos < LIST_CAP) g_i4List[pos] = s_stage[j];
    }
}

// ---------------------------------------------------------------------------
// Build the exact window histogram: re-read staged float4s (mostly coalesced
// since warp pushes are 32 consecutive i4s), bin in-window components.
__global__ void k_hist(const float4* __restrict__ x) {
    unsigned n = g_nList; if (n > LIST_CAP) n = LIST_CAP;
    unsigned lo = g_lo;
    int tid = blockIdx.x * blockDim.x + threadIdx.x;
    int stride = gridDim.x * blockDim.x;
    for (unsigned j = tid; j < n; j += stride) {
        unsigned i4 = g_i4List[j];
        float4 v = x[i4];
        unsigned b;
        b = (__float_as_uint(v.x) & 0x7FFFFFFFu) - lo;
        if (b < WIN_BINS) atomicAdd(&g_winHist[b], 1u);
        b = (__float_as_uint(v.y) & 0x7FFFFFFFu) - lo;
        if (b < WIN_BINS) atomicAdd(&g_winHist[b], 1u);
        b = (__float_as_uint(v.z) & 0x7FFFFFFFu) - lo;
        if (b < WIN_BINS) atomicAdd(&g_winHist[b], 1u);
        b = (__float_as_uint(v.w) & 0x7FFFFFFFu) - lo;
        if (b < WIN_BINS) atomicAdd(&g_winHist[b], 1u);
    }
}

// ---------------------------------------------------------------------------
__global__ void k_wreduce() {
    __shared__ unsigned int smr[256];
    unsigned int s = 0;
    int base = blockIdx.x * WCHUNK;
    for (int j = threadIdx.x; j < WCHUNK; j += 256) s += g_winHist[base + j];
    smr[threadIdx.x] = s;
    __syncthreads();
    for (int off = 128; off; off >>= 1) {
        if (threadIdx.x < off) smr[threadIdx.x] += smr[threadIdx.x + off];
        __syncthreads();
    }
    if (threadIdx.x == 0) g_chunkSum[blockIdx.x] = smr[0];
}

// ---------------------------------------------------------------------------
// Exact threshold T (31-bit key of k-th largest) + tie budget.
__global__ void k_wscan() {
    __shared__ unsigned int suf[1024];
    __shared__ int s_c;
    int t = threadIdx.x;

    suf[t] = g_chunkSum[t];
    __syncthreads();
    for (int d = 1; d < 1024; d <<= 1) {
        unsigned int v = (t + d < 1024) ? suf[t + d] : 0;
        __syncthreads();
        suf[t] += v;
        __syncthreads();
    }
    unsigned int above = g_above;
    long long kRem = (long long)K_TOP - (long long)above;
    unsigned int winTotal = suf[0];

    if (kRem < 1) {                    // degenerate: window missed low
        if (t == 0) { g_T = g_lo + WIN_BINS - 1; g_need = 0; }
        return;
    }
    if (kRem > (long long)winTotal) {  // degenerate: window missed high
        if (t == 0) { g_T = g_lo > 0 ? g_lo - 1 : 0; g_need = 0; }
        return;
    }
    unsigned int segAbove = (t < 1023) ? suf[t + 1] : 0;
    if ((long long)suf[t] >= kRem && (long long)segAbove < kRem) s_c = t;
    __syncthreads();
    int c = s_c;
    unsigned int baseAbove = (c < 1023) ? suf[c + 1] : 0;
    __syncthreads();

    suf[t] = g_winHist[c * WCHUNK + t];
    __syncthreads();
    for (int d = 1; d < 1024; d <<= 1) {
        unsigned int v = (t + d < 1024) ? suf[t + d] : 0;
        __syncthreads();
        suf[t] += v;
        __syncthreads();
    }
    unsigned int binAbove = baseAbove + ((t < 1023) ? suf[t + 1] : 0);
    if ((long long)(baseAbove + suf[t]) >= kRem && (long long)binAbove < kRem) {
        unsigned int bin = (unsigned)c * WCHUNK + (unsigned)t;
        g_T = g_lo + bin;
        g_need = (unsigned)(kRem - (long long)binAbove);
    }
}

// ---------------------------------------------------------------------------
// Fix-up: re-read staged float4s; write kept window components; collect ties.
__global__ void k_fix(const float4* __restrict__ x, float* __restrict__ out) {
    unsigned n = g_nList; if (n > LIST_CAP) n = LIST_CAP;
    unsigned lo = g_lo, T = g_T;
    int tid = blockIdx.x * blockDim.x + threadIdx.x;
    int stride = gridDim.x * blockDim.x;
    for (unsigned j = tid; j < n; j += stride) {
        unsigned i4 = g_i4List[j];
        float4 v = x[i4];
        unsigned raw[4] = { __float_as_uint(v.x), __float_as_uint(v.y),
                            __float_as_uint(v.z), __float_as_uint(v.w) };
#pragma unroll
        for (int c = 0; c < 4; c++) {
            unsigned b = raw[c] & 0x7FFFFFFFu;
            if ((b - lo) < WIN_BINS) {
                if (b > T) {
                    out[i4 * 4u + c] = __uint_as_float(raw[c]);
                } else if (b == T) {
                    unsigned p = atomicAdd(&g_eqCount, 1u);
                    if (p < EQ_CAP) { g_eqIdx[p] = i4 * 4u + c; g_eqVal[p] = raw[c]; }
                }
            }
        }
    }
}

// ---------------------------------------------------------------------------
// Ties at exactly T: keep the `need` smallest flat indices (lax.top_k order).
__global__ void k_tie(float* __restrict__ out) {
    unsigned int cnt = g_eqCount;
    if (cnt > EQ_CAP) cnt = EQ_CAP;
    unsigned int need = g_need;
    if (need == 0 || cnt == 0) return;
    if (need >= cnt) {
        for (unsigned i = threadIdx.x; i < cnt; i += blockDim.x)
            out[g_eqIdx[i]] = __uint_as_float(g_eqVal[i]);
        return;
    }
    for (unsigned i = threadIdx.x; i < cnt; i += blockDim.x) {
        unsigned idx = g_eqIdx[i];
        unsigned r = 0;
        for (unsigned j = 0; j < cnt; j++) r += (g_eqIdx[j] < idx) ? 1u : 0u;
        if (r < need) out[idx] = __uint_as_float(g_eqVal[i]);
    }
}

// ---------------------------------------------------------------------------
extern "C" void kernel_launch(void* const* d_in, const int* in_sizes, int n_in,
                              void* d_out, int out_size) {
    const float* x = (const float*)d_in[0];
    float* out = (float*)d_out;

    k_zero<<<256, 256>>>();
    k_sample<<<128, 256>>>((const float4*)x);
    k_sscan<<<1, 1024>>>();
    k_main<<<GRID_MAIN, BLK_MAIN>>>((const float4*)x, (float4*)out);
    k_hist<<<256, 256>>>((const float4*)x);
    k_wreduce<<<NCHUNKS, 256>>>();
    k_wscan<<<1, 1024>>>();
    k_fix<<<256, 256>>>((const float4*)x, out);
    k_tie<<<1, 256>>>(out);
}

// round 7
// speedup vs baseline: 1.0898x; 1.0898x over previous
#include <cuda_runtime.h>
#include <cstdint>

// Problem constants (fixed shape (8,2048,2048) fp32, ratio 0.1)
#define N_ELEMS   33554432
#define N_VEC4    (N_ELEMS / 4)
#define K_TOP     3355443           // int(0.1 * N)
#define SBINS     8192              // sample histogram bins (top 13 bits of 31-bit key)
#define SSHIFT    18
#define WIN_BINS  (1 << 20)         // window: 4 coarse sample bins = 2^20 key values
#define NBUCK     4096              // in-window buckets of 256 key values each
#define EQ_CAP    65536
#define LIST_CAP  (1 << 22)         // 4M staged (idx,val) entries (expected ~860K)
#define STAGE_CAP 2048              // per-block staging (mean ~840, huge margin)
#define SAMPLE_V4 262144            // 1/32 of float4s sampled
#define STARGET   (K_TOP / 32)

#define GRID_MAIN 1024              // 1024*256 = 262144 threads; N_VEC4 divisible
#define BLK_MAIN  256

__device__ unsigned int g_shist[SBINS];
__device__ unsigned int g_hA[NBUCK];
__device__ unsigned int g_above;
__device__ unsigned int g_lo;
__device__ int          g_bucket;    // coarse winning bucket (int for -1 sentinel)
__device__ unsigned int g_need;      // rank remainder within winning bucket
__device__ unsigned int g_nList;
__device__ uint2        g_list[LIST_CAP];
__device__ unsigned int g_eqCount;
__device__ uint2        g_eq[EQ_CAP];

// ---------------------------------------------------------------------------
__global__ void k_zero() {
    int tid = blockIdx.x * blockDim.x + threadIdx.x;
    int stride = gridDim.x * blockDim.x;
    for (int i = tid; i < SBINS; i += stride) g_shist[i] = 0;
    for (int i = tid; i < NBUCK; i += stride) g_hA[i] = 0;
    if (tid == 0) { g_above = 0; g_eqCount = 0; g_nList = 0; }
}

// ---------------------------------------------------------------------------
// Sample 1/32 of the data into a 13-bit shared histogram, flush to global.
__global__ void k_sample(const float4* __restrict__ x) {
    __shared__ unsigned int sh[SBINS];
    for (int i = threadIdx.x; i < SBINS; i += blockDim.x) sh[i] = 0;
    __syncthreads();

    int tid = blockIdx.x * blockDim.x + threadIdx.x;
    int stride = gridDim.x * blockDim.x;
    for (int i = tid; i < SAMPLE_V4; i += stride) {
        int p = ((i >> 6) << 11) + (i & 63);   // 64 f4 per 2048-f4 group
        float4 v = x[p];
        atomicAdd(&sh[(__float_as_uint(v.x) & 0x7FFFFFFFu) >> SSHIFT], 1u);
        atomicAdd(&sh[(__float_as_uint(v.y) & 0x7FFFFFFFu) >> SSHIFT], 1u);
        atomicAdd(&sh[(__float_as_uint(v.z) & 0x7FFFFFFFu) >> SSHIFT], 1u);
        atomicAdd(&sh[(__float_as_uint(v.w) & 0x7FFFFFFFu) >> SSHIFT], 1u);
    }
    __syncthreads();
    for (int i = threadIdx.x; i < SBINS; i += blockDim.x) {
        unsigned int c = sh[i];
        if (c) atomicAdd(&g_shist[i], c);
    }
}

// ---------------------------------------------------------------------------
// Locate the coarse sample bin of the estimated k-th value; open the window.
__global__ void k_sscan() {
    __shared__ unsigned int suf[1024];
    int t = threadIdx.x;
    unsigned int s = 0;
#pragma unroll
    for (int j = 0; j < 8; j++) s += g_shist[t * 8 + j];
    suf[t] = s;
    __syncthreads();
    for (int d = 1; d < 1024; d <<= 1) {
        unsigned int v = (t + d < 1024) ? suf[t + d] : 0;
        __syncthreads();
        suf[t] += v;
        __syncthreads();
    }
    unsigned int segAbove = (t < 1023) ? suf[t + 1] : 0;
    if (suf[t] >= (unsigned)STARGET && segAbove < (unsigned)STARGET) {
        unsigned int acc = segAbove;
        int bin = t * 8;
        for (int j = 7; j >= 0; j--) {
            acc += g_shist[t * 8 + j];
            if (acc >= (unsigned)STARGET) { bin = t * 8 + j; break; }
        }
        int lo_bin = bin >= 2 ? bin - 2 : 0;
        if (lo_bin > SBINS - 4) lo_bin = SBINS - 4;
        g_lo = (unsigned)lo_bin << SSHIFT;
    }
}

// ---------------------------------------------------------------------------
// FUSED streaming pass: read x, write provisional out (keep iff b>=hi),
// count 'above', histogram in-window elements into 4096 smem buckets, and
// stage (idx, rawbits) of in-window elements via warp prefix-scan push.
__device__ __forceinline__ unsigned proc_f4(
    float4 v, unsigned i4, unsigned lo, unsigned hi, unsigned lane,
    unsigned* s_hist, uint2* s_stage, unsigned* s_count,
    float4* __restrict__ out)
{
    unsigned r0 = __float_as_uint(v.x), r1 = __float_as_uint(v.y);
    unsigned r2 = __float_as_uint(v.z), r3 = __float_as_uint(v.w);
    unsigned b0 = r0 & 0x7FFFFFFFu, b1 = r1 & 0x7FFFFFFFu;
    unsigned b2 = r2 & 0x7FFFFFFFu, b3 = r3 & 0x7FFFFFFFu;
    float4 o;
    o.x = (b0 >= hi) ? v.x : 0.0f;
    o.y = (b1 >= hi) ? v.y : 0.0f;
    o.z = (b2 >= hi) ? v.z : 0.0f;
    o.w = (b3 >= hi) ? v.w : 0.0f;
    out[i4] = o;
    unsigned above = (b0 >= hi) + (b1 >= hi) + (b2 >= hi) + (b3 >= hi);

    bool w0 = (b0 - lo) < WIN_BINS, w1 = (b1 - lo) < WIN_BINS;
    bool w2 = (b2 - lo) < WIN_BINS, w3 = (b3 - lo) < WIN_BINS;
    unsigned cnt = (unsigned)w0 + w1 + w2 + w3;

    // warp inclusive scan of cnt
    unsigned scan = cnt;
#pragma unroll
    for (int d = 1; d < 32; d <<= 1) {
        unsigned t = __shfl_up_sync(0xFFFFFFFFu, scan, d);
        if (lane >= (unsigned)d) scan += t;
    }
    unsigned total = __shfl_sync(0xFFFFFFFFu, scan, 31);
    if (total) {
        unsigned base;
        if (lane == 31) base = atomicAdd(s_count, total);
        base = __shfl_sync(0xFFFFFFFFu, base, 31);
        unsigned p = base + scan - cnt;
        if (w0) { atomicAdd(&s_hist[(b0 - lo) >> 8], 1u);
                  if (p < STAGE_CAP) s_stage[p] = make_uint2(i4 * 4u + 0u, r0); p++; }
        if (w1) { atomicAdd(&s_hist[(b1 - lo) >> 8], 1u);
                  if (p < STAGE_CAP) s_stage[p] = make_uint2(i4 * 4u + 1u, r1); p++; }
        if (w2) { atomicAdd(&s_hist[(b2 - lo) >> 8], 1u);
                  if (p < STAGE_CAP) s_stage[p] = make_uint2(i4 * 4u + 2u, r2); p++; }
        if (w3) { atomicAdd(&s_hist[(b3 - lo) >> 8], 1u);
                  if (p < STAGE_CAP) s_stage[p] = make_uint2(i4 * 4u + 3u, r3); p++; }
    }
    return above;
}

__global__ void __launch_bounds__(BLK_MAIN) k_main(const float4* __restrict__ x,
                                                   float4* __restrict__ out) {
    __shared__ unsigned s_hist[NBUCK];
    __shared__ uint2    s_stage[STAGE_CAP];
    __shared__ unsigned s_count, s_above, s_base;

    for (int j = threadIdx.x; j < NBUCK; j += BLK_MAIN) s_hist[j] = 0;
    if (threadIdx.x == 0) { s_count = 0; s_above = 0; }
    __syncthreads();

    const unsigned lo = g_lo;
    const unsigned hi = lo + WIN_BINS;
    const unsigned lane = threadIdx.x & 31u;
    const unsigned stride = GRID_MAIN * BLK_MAIN;
    unsigned above = 0;

    unsigned i = blockIdx.x * blockDim.x + threadIdx.x;
    // N_VEC4 / stride == 32 exactly; unroll x2 with both loads hoisted (MLP)
    for (int it = 0; it < N_VEC4 / (2 * GRID_MAIN * BLK_MAIN); it++) {
        float4 v0 = x[i];
        float4 v1 = x[i + stride];
        above += proc_f4(v0, i, lo, hi, lane, s_hist, s_stage, &s_count, out);
        above += proc_f4(v1, i + stride, lo, hi, lane, s_hist, s_stage, &s_count, out);
        i += 2 * stride;
    }

#pragma unroll
    for (int off = 16; off; off >>= 1) above += __shfl_down_sync(0xFFFFFFFFu, above, off);
    if (lane == 0 && above) atomicAdd(&s_above, above);
    __syncthreads();

    if (threadIdx.x == 0) {
        if (s_above) atomicAdd(&g_above, s_above);
        unsigned n = s_count < STAGE_CAP ? s_count : STAGE_CAP;
        s_base = atomicAdd(&g_nList, n);
        s_count = n;
    }
    __syncthreads();

    // flush bucket histogram (skip zeros; ~800 nonzero of 4096)
    for (int j = threadIdx.x; j < NBUCK; j += BLK_MAIN) {
        unsigned c = s_hist[j];
        if (c) atomicAdd(&g_hA[j], c);
    }
    // flush staged entries
    unsigned n = s_count, base = s_base;
    for (unsigned j = threadIdx.x; j < n; j += BLK_MAIN) {
        unsigned pos = base + j;
        if (pos < LIST_CAP) g_list[pos] = s_stage[j];
    }
}

// ---------------------------------------------------------------------------
// Scan the 4096-bucket histogram from the top: winning bucket + rank remainder.
__global__ void k_sA() {
    __shared__ unsigned int suf[1024];
    int t = threadIdx.x;
    unsigned s = g_hA[4 * t] + g_hA[4 * t + 1] + g_hA[4 * t + 2] + g_hA[4 * t + 3];
    suf[t] = s;
    __syncthreads();
    for (int d = 1; d < 1024; d <<= 1) {
        unsigned int v = (t + d < 1024) ? suf[t + d] : 0;
        __syncthreads();
        suf[t] += v;
        __syncthreads();
    }
    long long kRem = (long long)K_TOP - (long long)g_above;
    unsigned winTotal = suf[0];

    if (kRem < 1) {                     // degenerate: nothing from window
        if (t == 0) { g_bucket = 0x7FFFFFFF; g_need = 0; }
        return;
    }
    if (kRem > (long long)winTotal) {   // degenerate: keep entire window
        if (t == 0) { g_bucket = -1; g_need = 0; }
        return;
    }
    unsigned segAbove = (t < 1023) ? suf[t + 1] : 0;
    if ((long long)suf[t] >= kRem && (long long)segAbove < kRem) {
        unsigned acc = segAbove;
        for (int j = 3; j >= 0; j--) {
            unsigned h = g_hA[4 * t + j];
            if ((long long)(acc + h) >= kRem) {
                g_bucket = 4 * t + j;
                g_need = (unsigned)(kRem - (long long)acc);
                break;
            }
            acc += h;
        }
    }
}

// ---------------------------------------------------------------------------
// One pass over the staged list: write sure keepers (bucket > c*), collect
// winning-bucket elements for exact selection.
__global__ void k_fix(float* __restrict__ out) {
    unsigned n = g_nList; if (n > LIST_CAP) n = LIST_CAP;
    unsigned lo = g_lo;
    int cstar = g_bucket;
    int tid = blockIdx.x * blockDim.x + threadIdx.x;
    int stride = gridDim.x * blockDim.x;
    for (unsigned j = tid; j < n; j += stride) {
        uint2 e = g_list[j];
        unsigned b = e.y & 0x7FFFFFFFu;
        int bucket = (int)((b - lo) >> 8);
        if (bucket > cstar) {
            out[e.x] = __uint_as_float(e.y);
        } else if (bucket == cstar) {
            unsigned p = atomicAdd(&g_eqCount, 1u);
            if (p < EQ_CAP) g_eq[p] = e;
        }
    }
}

// ---------------------------------------------------------------------------
// Exact selection within the winning bucket (~210 elements): keep the `need`
// best by (|value| desc, index asc) — matches lax.top_k stable ordering.
__global__ void k_sel(float* __restrict__ out) {
    unsigned cnt = g_eqCount; if (cnt > EQ_CAP) cnt = EQ_CAP;
    unsigned need = g_need;
    if (need == 0 || cnt == 0) return;
    for (unsigned i = threadIdx.x; i < cnt; i += blockDim.x) {
        uint2 ei = g_eq[i];
        unsigned bi = ei.y & 0x7FFFFFFFu;
        unsigned rank = 0;
        for (unsigned j = 0; j < cnt; j++) {
            uint2 ej = g_eq[j];
            unsigned bj = ej.y & 0x7FFFFFFFu;
            rank += (bj > bi) || (bj == bi && ej.x < ei.x);
        }
        if (rank < need) out[ei.x] = __uint_as_float(ei.y);
    }
}

// ---------------------------------------------------------------------------
extern "C" void kernel_launch(void* const* d_in, const int* in_sizes, int n_in,
                              void* d_out, int out_size) {
    const float* x = (const float*)d_in[0];
    float* out = (float*)d_out;

    k_zero<<<32, 256>>>();
    k_sample<<<128, 256>>>((const float4*)x);
    k_sscan<<<1, 1024>>>();
    k_main<<<GRID_MAIN, BLK_MAIN>>>((const float4*)x, (float4*)out);
    k_sA<<<1, 1024>>>();
    k_fix<<<256, 256>>>(out);
    k_sel<<<1, 256>>>(out);
}